// round 11
// baseline (speedup 1.0000x reference)
#include <cuda_runtime.h>
#include <cstdint>

#define NV      400000
#define CIN     64
#define COUT    64
#define KT      27
#define TILE_M  128
#define THREADS 128

#define FS_PAD 68      // Fs row stride (words)
#define WS_PAD 72      // Ws row stride (words)
#define FS_WORDS (TILE_M * FS_PAD)   // 8704
#define WS_WORDS (CIN * WS_PAD)      // 4608
#define BUF_WORDS (FS_WORDS + WS_WORDS)      // 13312
#define SMEM_BYTES (2 * BUF_WORDS * 4)       // 106496 -> 2 CTAs/SM

// ---------------- device globals: pre-converted tf32 copies ----------------
__device__ float g_feats[(size_t)NV * CIN];
__device__ float g_w[KT * CIN * COUT];

__device__ __forceinline__ uint32_t cvt_tf32(float x) {
    uint32_t u;
    asm("cvt.rna.tf32.f32 %0, %1;" : "=r"(u) : "f"(x));
    return u;
}
__device__ __forceinline__ uint32_t smem_u32(const void* p) {
    uint32_t a;
    asm("{ .reg .u64 t; cvta.to.shared.u64 t, %1; cvt.u32.u64 %0, t; }" : "=r"(a) : "l"(p));
    return a;
}
__device__ __forceinline__ void cp_async16(uint32_t dst, const void* src, uint32_t src_bytes) {
    asm volatile("cp.async.cg.shared.global [%0], [%1], 16, %2;"
                 :: "r"(dst), "l"(src), "r"(src_bytes) : "memory");
}
__device__ __forceinline__ void cp_commit() {
    asm volatile("cp.async.commit_group;" ::: "memory");
}
template <int N>
__device__ __forceinline__ void cp_wait() {
    asm volatile("cp.async.wait_group %0;" :: "n"(N) : "memory");
}
__device__ __forceinline__ void mma_tf32(float* d, const uint32_t* a, const uint32_t* b) {
    asm volatile(
        "mma.sync.aligned.m16n8k8.row.col.f32.tf32.tf32.f32 "
        "{%0,%1,%2,%3}, {%4,%5,%6,%7}, {%8,%9}, {%0,%1,%2,%3};"
        : "+f"(d[0]), "+f"(d[1]), "+f"(d[2]), "+f"(d[3])
        : "r"(a[0]), "r"(a[1]), "r"(a[2]), "r"(a[3]), "r"(b[0]), "r"(b[1]));
}

// ---------------- prep kernels (tf32 round once) ----------------
__global__ void prep_feats(const float4* __restrict__ f) {
    size_t i = (size_t)blockIdx.x * 256 + threadIdx.x;   // NV*CIN/4 chunks
    const float4 v = f[i];
    uint4 u;
    u.x = cvt_tf32(v.x); u.y = cvt_tf32(v.y);
    u.z = cvt_tf32(v.z); u.w = cvt_tf32(v.w);
    reinterpret_cast<uint4*>(g_feats)[i] = u;
}
__global__ void prep_w(const float* __restrict__ w) {
    int i = blockIdx.x * 256 + threadIdx.x;              // KT*CIN*COUT
    g_w[i] = __uint_as_float(cvt_tf32(w[i]));
}

// ---------------- main kernel ----------------
// CTA: 128 threads = 4 warps, tile M=128 x N=64, K-SPLIT warp pairs:
//   warp = mstripe*2 + khalf.  Each warp computes a 64x64 output tile over
//   HALF of cin (K=32).  mt=4, nt=8, 4 k-steps.  Partner pairs reduce via
//   smem at the end.  53KB smem/buf*2 -> 2 CTAs/SM (2 warps/SMSP).
__global__ __launch_bounds__(THREADS, 2)
void spconv_pipe(const float* __restrict__ bias,
                 const int*   __restrict__ nbr,
                 float*       __restrict__ out)
{
    extern __shared__ uint32_t smem[];
    const uint32_t smem_base = smem_u32(smem);

    const int tid   = threadIdx.x;
    const int warp  = tid >> 5;
    const int lane  = tid & 31;
    const int lq    = lane >> 2;
    const int lr    = lane & 3;
    const int mstripe = warp >> 1;            // 0..1 : which 64 voxels
    const int khalf   = warp & 1;             // 0..1 : which 32 cin
    const int vb    = mstripe * 64;
    const int kbase = khalf * 32;
    const int jbase = blockIdx.x * TILE_M;

    // accumulators: khalf==0 seeded with bias, khalf==1 with zero
    float acc[4][8][4];
    #pragma unroll
    for (int nt = 0; nt < 8; ++nt) {
        const float bx = khalf ? 0.f : __ldg(bias + nt * 8 + lr * 2);
        const float by = khalf ? 0.f : __ldg(bias + nt * 8 + lr * 2 + 1);
        #pragma unroll
        for (int mt = 0; mt < 4; ++mt) {
            acc[mt][nt][0] = bx; acc[mt][nt][1] = by;
            acc[mt][nt][2] = bx; acc[mt][nt][3] = by;
        }
    }

    // ---- staging: thread owns row tid (16 chunks) + 8 W chunks ----
    const int jrow = jbase + tid;
    const bool row_ok = jrow < NV;
    auto load_idx = [&](int k) -> int {
        return row_ok ? __ldg(nbr + (size_t)k * NV + jrow) : -1;
    };
    auto stage = [&](int k, int buf, int idx) {
        const uint32_t fbase = smem_base + (buf * BUF_WORDS) * 4;
        const uint32_t wbase = fbase + FS_WORDS * 4;
        const uint32_t sz = (idx >= 0) ? 16u : 0u;
        const float* src = g_feats + (size_t)(idx < 0 ? 0 : idx) * CIN;
        const uint32_t dst0 = fbase + (tid * FS_PAD) * 4;
        #pragma unroll
        for (int c = 0; c < 16; ++c)
            cp_async16(dst0 + c * 16, src + c * 4, sz);
        const float* wsrc = g_w + (size_t)k * (CIN * COUT);
        #pragma unroll
        for (int r = 0; r < 8; ++r) {
            const int l = tid + r * THREADS;   // 0..1023
            cp_async16(wbase + ((l >> 4) * WS_PAD + (l & 15) * 4) * 4,
                       wsrc + l * 4, 16u);
        }
    };

    // prologue
    stage(0, 0, load_idx(0));
    cp_commit();
    int idx_nxt = load_idx(1);

    for (int k = 0; k < KT; ++k) {
        const int cb = k & 1;
        __syncthreads();                 // done reading buffer cb (tap k-2)

        if (k + 1 < KT) {
            stage(k + 1, cb ^ 1, idx_nxt);
            cp_commit();
            if (k + 2 < KT) idx_nxt = load_idx(k + 2);
            cp_wait<1>();
        } else {
            cp_wait<0>();
        }
        __syncthreads();

        const uint32_t* Fs = smem + cb * BUF_WORDS;
        const uint32_t* Ws = Fs + FS_WORDS;
        #pragma unroll
        for (int ks = 0; ks < 4; ++ks) {
            const int kb = kbase + ks * 8;
            uint32_t b[8][2];
            #pragma unroll
            for (int nt = 0; nt < 8; ++nt) {
                const int ncol = nt * 8 + lq;
                b[nt][0] = Ws[(kb + lr)     * WS_PAD + ncol];
                b[nt][1] = Ws[(kb + lr + 4) * WS_PAD + ncol];
            }
            #pragma unroll
            for (int mt = 0; mt < 4; ++mt) {
                uint32_t a[4];
                const int base = (vb + mt * 16 + lq) * FS_PAD + kb + lr;
                a[0] = Fs[base];
                a[1] = Fs[base + 8 * FS_PAD];
                a[2] = Fs[base + 4];
                a[3] = Fs[base + 8 * FS_PAD + 4];
                #pragma unroll
                for (int nt = 0; nt < 8; ++nt)
                    mma_tf32(acc[mt][nt], a, b[nt]);
            }
        }
    }

    // ---- K-split reduction: khalf==1 writes partials to smem, khalf==0 adds ----
    __syncthreads();                          // all compute on smem buffers done
    float* Ps = reinterpret_cast<float*>(smem);   // reuse [128][FS_PAD]
    if (khalf == 1) {
        #pragma unroll
        for (int mt = 0; mt < 4; ++mt) {
            const int r0 = vb + mt * 16 + lq;
            #pragma unroll
            for (int nt = 0; nt < 8; ++nt) {
                const int col = nt * 8 + lr * 2;
                *reinterpret_cast<float2*>(&Ps[r0 * FS_PAD + col]) =
                    make_float2(acc[mt][nt][0], acc[mt][nt][1]);
                *reinterpret_cast<float2*>(&Ps[(r0 + 8) * FS_PAD + col]) =
                    make_float2(acc[mt][nt][2], acc[mt][nt][3]);
            }
        }
    }
    __syncthreads();

    if (khalf == 0) {
        #pragma unroll
        for (int mt = 0; mt < 4; ++mt) {
            const int r0 = vb + mt * 16 + lq;
            const int g0 = jbase + r0;
            const bool ok0 = g0 < NV;
            const bool ok1 = (g0 + 8) < NV;
            #pragma unroll
            for (int nt = 0; nt < 8; ++nt) {
                const int col = nt * 8 + lr * 2;
                const float2 p0 = *reinterpret_cast<const float2*>(&Ps[r0 * FS_PAD + col]);
                const float2 p1 = *reinterpret_cast<const float2*>(&Ps[(r0 + 8) * FS_PAD + col]);
                if (ok0) {
                    float2 o = make_float2(acc[mt][nt][0] + p0.x, acc[mt][nt][1] + p0.y);
                    *reinterpret_cast<float2*>(out + (size_t)g0 * COUT + col) = o;
                }
                if (ok1) {
                    float2 o = make_float2(acc[mt][nt][2] + p1.x, acc[mt][nt][3] + p1.y);
                    *reinterpret_cast<float2*>(out + (size_t)(g0 + 8) * COUT + col) = o;
                }
            }
        }
    }
}

extern "C" void kernel_launch(void* const* d_in, const int* in_sizes, int n_in,
                              void* d_out, int out_size) {
    const float* feats  = (const float*)d_in[0];   // [N, 64] f32
    const float* weight = (const float*)d_in[1];   // [27, 64, 64] f32
    const float* bias   = (const float*)d_in[2];   // [64] f32
    const int*   nbr    = (const int*)  d_in[3];   // [27, N] i32
    float*       out    = (float*)d_out;           // [N, 64] f32

    static bool init_done = false;
    if (!init_done) {
        cudaFuncSetAttribute(spconv_pipe,
                             cudaFuncAttributeMaxDynamicSharedMemorySize, SMEM_BYTES);
        init_done = true;
    }
    prep_feats<<<(NV * CIN / 4) / 256, 256>>>(reinterpret_cast<const float4*>(feats));
    prep_w<<<(KT * CIN * COUT) / 256, 256>>>(weight);
    const int grid = (NV + TILE_M - 1) / TILE_M;   // 3125
    spconv_pipe<<<grid, THREADS, SMEM_BYTES>>>(bias, nbr, out);
}

// round 12
// speedup vs baseline: 1.0095x; 1.0095x over previous
#include <cuda_runtime.h>
#include <cstdint>

#define NV      400000
#define CIN     64
#define COUT    64
#define KT      27
#define TILE_M  128
#define THREADS 128

#define FS_PAD 68      // Fs row stride (words)
#define WS_PAD 72      // Ws row stride (words)
#define FS_WORDS (TILE_M * FS_PAD)   // 8704
#define WS_WORDS (CIN * WS_PAD)      // 4608
#define BUF_WORDS (FS_WORDS + WS_WORDS)      // 13312
#define SMEM_BYTES (2 * BUF_WORDS * 4)       // 106496 -> 2 CTAs/SM

// ---------------- device globals: pre-converted tf32 copies ----------------
__device__ float g_feats[(size_t)NV * CIN];
__device__ float g_w[KT * CIN * COUT];

__device__ __forceinline__ uint32_t cvt_tf32(float x) {
    uint32_t u;
    asm("cvt.rna.tf32.f32 %0, %1;" : "=r"(u) : "f"(x));
    return u;
}
__device__ __forceinline__ uint32_t smem_u32(const void* p) {
    uint32_t a;
    asm("{ .reg .u64 t; cvta.to.shared.u64 t, %1; cvt.u32.u64 %0, t; }" : "=r"(a) : "l"(p));
    return a;
}
__device__ __forceinline__ void cp_async16(uint32_t dst, const void* src, uint32_t src_bytes) {
    asm volatile("cp.async.cg.shared.global [%0], [%1], 16, %2;"
                 :: "r"(dst), "l"(src), "r"(src_bytes) : "memory");
}
__device__ __forceinline__ void cp_commit() {
    asm volatile("cp.async.commit_group;" ::: "memory");
}
template <int N>
__device__ __forceinline__ void cp_wait() {
    asm volatile("cp.async.wait_group %0;" :: "n"(N) : "memory");
}
__device__ __forceinline__ void mma_tf32(float* d, const uint32_t* a, const uint32_t* b) {
    asm volatile(
        "mma.sync.aligned.m16n8k8.row.col.f32.tf32.tf32.f32 "
        "{%0,%1,%2,%3}, {%4,%5,%6,%7}, {%8,%9}, {%0,%1,%2,%3};"
        : "+f"(d[0]), "+f"(d[1]), "+f"(d[2]), "+f"(d[3])
        : "r"(a[0]), "r"(a[1]), "r"(a[2]), "r"(a[3]), "r"(b[0]), "r"(b[1]));
}

// ---------------- prep kernels (tf32 round once) ----------------
__global__ void prep_feats(const float4* __restrict__ f) {
    size_t i = (size_t)blockIdx.x * 256 + threadIdx.x;   // NV*CIN/4 chunks
    const float4 v = f[i];
    uint4 u;
    u.x = cvt_tf32(v.x); u.y = cvt_tf32(v.y);
    u.z = cvt_tf32(v.z); u.w = cvt_tf32(v.w);
    reinterpret_cast<uint4*>(g_feats)[i] = u;
}
__global__ void prep_w(const float* __restrict__ w) {
    int i = blockIdx.x * 256 + threadIdx.x;              // KT*CIN*COUT
    g_w[i] = __uint_as_float(cvt_tf32(w[i]));
}

// ---------------- main kernel ----------------
// CTA: 128 threads = 4 warps, tile M=128 x N=64. Warp w owns voxels
// [w*32, w*32+32) x ALL 64 couts: mt=2, nt=8. 53KB/buf x2 -> 2 CTAs/SM.
// Gather: COALESCED 16-lanes-per-row (each cp.async instr = 2 full rows
// = 4 cache lines, vs 32 line-touches for the one-thread-per-row layout).
__global__ __launch_bounds__(THREADS, 2)
void spconv_pipe(const float* __restrict__ bias,
                 const int*   __restrict__ nbr,
                 float*       __restrict__ out)
{
    extern __shared__ uint32_t smem[];
    const uint32_t smem_base = smem_u32(smem);

    const int tid  = threadIdx.x;
    const int warp = tid >> 5;
    const int lane = tid & 31;
    const int lq   = lane >> 2;
    const int lr   = lane & 3;
    const int vb   = warp * 32;               // warp's 32-voxel stripe
    const int jbase = blockIdx.x * TILE_M;    // NV % TILE_M == 0: no guards

    // gather geometry: 16 lanes per row
    const int f4   = tid & 15;                // 16B chunk within row
    const int rowg = tid >> 4;                // row group 0..7

    // accumulators seeded with bias
    float acc[2][8][4];
    #pragma unroll
    for (int nt = 0; nt < 8; ++nt) {
        const float bx = __ldg(bias + nt * 8 + lr * 2);
        const float by = __ldg(bias + nt * 8 + lr * 2 + 1);
        #pragma unroll
        for (int mt = 0; mt < 2; ++mt) {
            acc[mt][nt][0] = bx; acc[mt][nt][1] = by;
            acc[mt][nt][2] = bx; acc[mt][nt][3] = by;
        }
    }

    // ---- idx prefetch: 16 rows per lane-group (same value across 16 lanes) ----
    int idxs[16];
    auto load_idxs = [&](int k) {
        const int* nk = nbr + (size_t)k * NV + jbase + rowg;
        #pragma unroll
        for (int it = 0; it < 16; ++it)
            idxs[it] = __ldg(nk + 8 * it);
    };

    // ---- staging: coalesced gather + W copy ----
    auto stage = [&](int k, int buf) {
        const uint32_t fbase = smem_base + (buf * BUF_WORDS) * 4;
        const uint32_t wbase = fbase + FS_WORDS * 4;
        #pragma unroll
        for (int it = 0; it < 16; ++it) {
            const int v   = rowg + 8 * it;
            const int idx = idxs[it];
            const float* src = g_feats + (size_t)(idx < 0 ? 0 : idx) * CIN + f4 * 4;
            cp_async16(fbase + (v * FS_PAD + f4 * 4) * 4, src, idx >= 0 ? 16u : 0u);
        }
        const float* wsrc = g_w + (size_t)k * (CIN * COUT);
        #pragma unroll
        for (int r = 0; r < 8; ++r) {
            const int l = tid + r * THREADS;   // 0..1023
            cp_async16(wbase + ((l >> 4) * WS_PAD + (l & 15) * 4) * 4,
                       wsrc + l * 4, 16u);
        }
    };

    // prologue: idx0 -> stage0 -> commit -> idx1
    load_idxs(0);
    stage(0, 0);
    cp_commit();
    load_idxs(1);

    for (int k = 0; k < KT; ++k) {
        const int cb = k & 1;
        __syncthreads();                 // done reading buffer cb (tap k-2)

        if (k + 1 < KT) {
            stage(k + 1, cb ^ 1);        // uses idxs loaded last iteration
            cp_commit();
            if (k + 2 < KT) load_idxs(k + 2);   // latency hidden by compute
            cp_wait<1>();
        } else {
            cp_wait<0>();
        }
        __syncthreads();

        const uint32_t* Fs = smem + cb * BUF_WORDS;
        const uint32_t* Ws = Fs + FS_WORDS;
        #pragma unroll
        for (int ks = 0; ks < 8; ++ks) {
            const int kb = ks * 8;
            uint32_t b[8][2];
            #pragma unroll
            for (int nt = 0; nt < 8; ++nt) {
                const int ncol = nt * 8 + lq;
                b[nt][0] = Ws[(kb + lr)     * WS_PAD + ncol];
                b[nt][1] = Ws[(kb + lr + 4) * WS_PAD + ncol];
            }
            #pragma unroll
            for (int mt = 0; mt < 2; ++mt) {
                uint32_t a[4];
                const int base = (vb + mt * 16 + lq) * FS_PAD + kb + lr;
                a[0] = Fs[base];
                a[1] = Fs[base + 8 * FS_PAD];
                a[2] = Fs[base + 4];
                a[3] = Fs[base + 8 * FS_PAD + 4];
                #pragma unroll
                for (int nt = 0; nt < 8; ++nt)
                    mma_tf32(acc[mt][nt], a, b[nt]);
            }
        }
    }

    // ---- epilogue: store float2 pairs (bias already folded in; no guards) ----
    #pragma unroll
    for (int mt = 0; mt < 2; ++mt) {
        const int r0 = jbase + vb + mt * 16 + lq;
        #pragma unroll
        for (int nt = 0; nt < 8; ++nt) {
            const int col = nt * 8 + lr * 2;
            float2 o0 = make_float2(acc[mt][nt][0], acc[mt][nt][1]);
            float2 o1 = make_float2(acc[mt][nt][2], acc[mt][nt][3]);
            *reinterpret_cast<float2*>(out + (size_t)r0 * COUT + col)       = o0;
            *reinterpret_cast<float2*>(out + (size_t)(r0 + 8) * COUT + col) = o1;
        }
    }
}

extern "C" void kernel_launch(void* const* d_in, const int* in_sizes, int n_in,
                              void* d_out, int out_size) {
    const float* feats  = (const float*)d_in[0];   // [N, 64] f32
    const float* weight = (const float*)d_in[1];   // [27, 64, 64] f32
    const float* bias   = (const float*)d_in[2];   // [64] f32
    const int*   nbr    = (const int*)  d_in[3];   // [27, N] i32
    float*       out    = (float*)d_out;           // [N, 64] f32

    static bool init_done = false;
    if (!init_done) {
        cudaFuncSetAttribute(spconv_pipe,
                             cudaFuncAttributeMaxDynamicSharedMemorySize, SMEM_BYTES);
        init_done = true;
    }
    prep_feats<<<(NV * CIN / 4) / 256, 256>>>(reinterpret_cast<const float4*>(feats));
    prep_w<<<(KT * CIN * COUT) / 256, 256>>>(weight);
    spconv_pipe<<<NV / TILE_M, THREADS, SMEM_BYTES>>>(bias, nbr, out);
}

// round 13
// speedup vs baseline: 1.0334x; 1.0236x over previous
#include <cuda_runtime.h>
#include <cstdint>

#define NV      400000
#define CIN     64
#define COUT    64
#define KT      27
#define TILE_M  128
#define THREADS 128

#define FS_PAD 68      // Fs row stride (words)
#define WS_PAD 72      // Ws row stride (words)
#define FS_WORDS (TILE_M * FS_PAD)   // 8704
#define WS_WORDS (CIN * WS_PAD)      // 4608
#define BUF_WORDS (FS_WORDS + WS_WORDS)      // 13312
#define SMEM_BYTES (2 * BUF_WORDS * 4)       // 106496 -> 2 CTAs/SM

// ---------------- device global: pre-converted tf32 weights only ----------------
__device__ float g_w[KT * CIN * COUT];

__device__ __forceinline__ uint32_t cvt_tf32(float x) {
    uint32_t u;
    asm("cvt.rna.tf32.f32 %0, %1;" : "=r"(u) : "f"(x));
    return u;
}
__device__ __forceinline__ uint32_t smem_u32(const void* p) {
    uint32_t a;
    asm("{ .reg .u64 t; cvta.to.shared.u64 t, %1; cvt.u32.u64 %0, t; }" : "=r"(a) : "l"(p));
    return a;
}
__device__ __forceinline__ void cp_async16(uint32_t dst, const void* src, uint32_t src_bytes) {
    asm volatile("cp.async.cg.shared.global [%0], [%1], 16, %2;"
                 :: "r"(dst), "l"(src), "r"(src_bytes) : "memory");
}
__device__ __forceinline__ void cp_commit() {
    asm volatile("cp.async.commit_group;" ::: "memory");
}
template <int N>
__device__ __forceinline__ void cp_wait() {
    asm volatile("cp.async.wait_group %0;" :: "n"(N) : "memory");
}
__device__ __forceinline__ void mma_tf32(float* d, const uint32_t* a, const uint32_t* b) {
    asm volatile(
        "mma.sync.aligned.m16n8k8.row.col.f32.tf32.tf32.f32 "
        "{%0,%1,%2,%3}, {%4,%5,%6,%7}, {%8,%9}, {%0,%1,%2,%3};"
        : "+f"(d[0]), "+f"(d[1]), "+f"(d[2]), "+f"(d[3])
        : "r"(a[0]), "r"(a[1]), "r"(a[2]), "r"(a[3]), "r"(b[0]), "r"(b[1]));
}

// ---------------- prep kernel: weights -> tf32 (tiny) ----------------
__global__ void prep_w(const float* __restrict__ w) {
    int i = blockIdx.x * 256 + threadIdx.x;              // KT*CIN*COUT
    g_w[i] = __uint_as_float(cvt_tf32(w[i]));
}

// ---------------- main kernel ----------------
// CTA: 128 threads = 4 warps, tile M=128 x N=64. Warp w owns voxels
// [w*32, w*32+32) x ALL 64 couts: mt=2, nt=8. 53KB/buf x2 -> 2 CTAs/SM.
// Gather: coalesced 16-lanes-per-row, RAW fp32 feats (no copy);
// A-fragments converted to tf32 (rna) in-register before each MMA.
__global__ __launch_bounds__(THREADS, 2)
void spconv_pipe(const float* __restrict__ feats,
                 const float* __restrict__ bias,
                 const int*   __restrict__ nbr,
                 float*       __restrict__ out)
{
    extern __shared__ uint32_t smem[];
    const uint32_t smem_base = smem_u32(smem);

    const int tid  = threadIdx.x;
    const int warp = tid >> 5;
    const int lane = tid & 31;
    const int lq   = lane >> 2;
    const int lr   = lane & 3;
    const int vb   = warp * 32;               // warp's 32-voxel stripe
    const int jbase = blockIdx.x * TILE_M;    // NV % TILE_M == 0: no guards

    // gather geometry: 16 lanes per row
    const int f4   = tid & 15;                // 16B chunk within row
    const int rowg = tid >> 4;                // row group 0..7

    // accumulators seeded with bias
    float acc[2][8][4];
    #pragma unroll
    for (int nt = 0; nt < 8; ++nt) {
        const float bx = __ldg(bias + nt * 8 + lr * 2);
        const float by = __ldg(bias + nt * 8 + lr * 2 + 1);
        #pragma unroll
        for (int mt = 0; mt < 2; ++mt) {
            acc[mt][nt][0] = bx; acc[mt][nt][1] = by;
            acc[mt][nt][2] = bx; acc[mt][nt][3] = by;
        }
    }

    // ---- idx prefetch: 16 rows per lane-group ----
    int idxs[16];
    auto load_idxs = [&](int k) {
        const int* nk = nbr + (size_t)k * NV + jbase + rowg;
        #pragma unroll
        for (int it = 0; it < 16; ++it)
            idxs[it] = __ldg(nk + 8 * it);
    };

    // ---- staging: coalesced gather (raw fp32) + W copy (tf32) ----
    auto stage = [&](int k, int buf) {
        const uint32_t fbase = smem_base + (buf * BUF_WORDS) * 4;
        const uint32_t wbase = fbase + FS_WORDS * 4;
        #pragma unroll
        for (int it = 0; it < 16; ++it) {
            const int v   = rowg + 8 * it;
            const int idx = idxs[it];
            const float* src = feats + (size_t)(idx < 0 ? 0 : idx) * CIN + f4 * 4;
            cp_async16(fbase + (v * FS_PAD + f4 * 4) * 4, src, idx >= 0 ? 16u : 0u);
        }
        const float* wsrc = g_w + (size_t)k * (CIN * COUT);
        #pragma unroll
        for (int r = 0; r < 8; ++r) {
            const int l = tid + r * THREADS;   // 0..1023
            cp_async16(wbase + ((l >> 4) * WS_PAD + (l & 15) * 4) * 4,
                       wsrc + l * 4, 16u);
        }
    };

    // prologue: idx0 -> stage0 -> commit -> idx1
    load_idxs(0);
    stage(0, 0);
    cp_commit();
    load_idxs(1);

    for (int k = 0; k < KT; ++k) {
        const int cb = k & 1;
        __syncthreads();                 // done reading buffer cb (tap k-2)

        if (k + 1 < KT) {
            stage(k + 1, cb ^ 1);        // uses idxs loaded last iteration
            cp_commit();
            if (k + 2 < KT) load_idxs(k + 2);   // latency hidden by compute
            cp_wait<1>();
        } else {
            cp_wait<0>();
        }
        __syncthreads();

        const uint32_t* Fs = smem + cb * BUF_WORDS;
        const uint32_t* Ws = Fs + FS_WORDS;
        #pragma unroll
        for (int ks = 0; ks < 8; ++ks) {
            const int kb = ks * 8;
            uint32_t b[8][2];
            #pragma unroll
            for (int nt = 0; nt < 8; ++nt) {
                const int ncol = nt * 8 + lq;
                b[nt][0] = Ws[(kb + lr)     * WS_PAD + ncol];
                b[nt][1] = Ws[(kb + lr + 4) * WS_PAD + ncol];
            }
            #pragma unroll
            for (int mt = 0; mt < 2; ++mt) {
                uint32_t a[4];
                const int base = (vb + mt * 16 + lq) * FS_PAD + kb + lr;
                a[0] = Fs[base];
                a[1] = Fs[base + 8 * FS_PAD];
                a[2] = Fs[base + 4];
                a[3] = Fs[base + 8 * FS_PAD + 4];
                // convert raw fp32 activations to tf32 (rna) in-register
                a[0] = cvt_tf32(__uint_as_float(a[0]));
                a[1] = cvt_tf32(__uint_as_float(a[1]));
                a[2] = cvt_tf32(__uint_as_float(a[2]));
                a[3] = cvt_tf32(__uint_as_float(a[3]));
                #pragma unroll
                for (int nt = 0; nt < 8; ++nt)
                    mma_tf32(acc[mt][nt], a, b[nt]);
            }
        }
    }

    // ---- epilogue: store float2 pairs (bias already folded in; no guards) ----
    #pragma unroll
    for (int mt = 0; mt < 2; ++mt) {
        const int r0 = jbase + vb + mt * 16 + lq;
        #pragma unroll
        for (int nt = 0; nt < 8; ++nt) {
            const int col = nt * 8 + lr * 2;
            float2 o0 = make_float2(acc[mt][nt][0], acc[mt][nt][1]);
            float2 o1 = make_float2(acc[mt][nt][2], acc[mt][nt][3]);
            *reinterpret_cast<float2*>(out + (size_t)r0 * COUT + col)       = o0;
            *reinterpret_cast<float2*>(out + (size_t)(r0 + 8) * COUT + col) = o1;
        }
    }
}

extern "C" void kernel_launch(void* const* d_in, const int* in_sizes, int n_in,
                              void* d_out, int out_size) {
    const float* feats  = (const float*)d_in[0];   // [N, 64] f32
    const float* weight = (const float*)d_in[1];   // [27, 64, 64] f32
    const float* bias   = (const float*)d_in[2];   // [64] f32
    const int*   nbr    = (const int*)  d_in[3];   // [27, N] i32
    float*       out    = (float*)d_out;           // [N, 64] f32

    static bool init_done = false;
    if (!init_done) {
        cudaFuncSetAttribute(spconv_pipe,
                             cudaFuncAttributeMaxDynamicSharedMemorySize, SMEM_BYTES);
        init_done = true;
    }
    prep_w<<<(KT * CIN * COUT) / 256, 256>>>(weight);
    spconv_pipe<<<NV / TILE_M, THREADS, SMEM_BYTES>>>(feats, bias, nbr, out);
}